// round 7
// baseline (speedup 1.0000x reference)
#include <cuda_runtime.h>
#include <cstdint>

#define NB 4096
#define NR 64
#define ND 512
#define D2 256              // ND/2
#define BPC 32              // b-rows per CTA
#define GRID (NB / BPC)     // 128

typedef unsigned long long u64;

__device__ __forceinline__ void fma2(u64 &d, u64 a, u64 b) {
    asm("fma.rn.f32x2 %0, %1, %2, %0;" : "+l"(d) : "l"(a), "l"(b));
}
__device__ __forceinline__ u64 add2(u64 a, u64 b) {
    u64 r; asm("add.rn.f32x2 %0, %1, %2;" : "=l"(r) : "l"(a), "l"(b)); return r;
}
__device__ __forceinline__ float hsum2(u64 a) {
    float x, y;
    asm("mov.b64 {%0, %1}, %2;" : "=f"(x), "=f"(y) : "l"(a));
    return x + y;
}

__device__ float g_part[GRID];
__device__ int   g_ctr = 0;

// ---- dynamic smem layout (bytes) ----
#define OFF_E   0
#define SZ_E    (D2 * 512)              // [d2][r] float2 rows, 512B each = 131072
#define OFF_W   (OFF_E + SZ_E)          // chunk-major: [128 d-chunks][32 b] float4
#define SZ_W    (128 * 32 * 16)         // 65536
#define OFF_P   (OFF_W + SZ_W)          // split-K partials [32 b][32 lane] ulonglong2
#define SZ_P    (32 * 32 * 16)          // 16384
#define OFF_EN  (OFF_P + SZ_P)          // 64 f
#define OFF_WN  (OFF_EN + 256)          // 32 f
#define OFF_Y   (OFF_WN + 128)          // 32 i
#define OFF_LS  (OFF_Y + 128)           // 32 f
#define OFF_PE  (OFF_LS + 128)          // 256 f
#define OFF_PW  (OFF_PE + 1024)         // 256 f
#define SMEM_TOTAL (OFF_PW + 1024)      // 215680 B

__global__ __launch_bounds__(256, 1)
void k_fused(const float* __restrict__ W, const float* __restrict__ E,
             const float* __restrict__ Lb, float* __restrict__ pred,
             float* __restrict__ lossp) {
    extern __shared__ char sm[];
    float*      sE  = (float*)(sm + OFF_E);
    float4*     sW4 = (float4*)(sm + OFF_W);
    ulonglong2* sP  = (ulonglong2*)(sm + OFF_P);
    float* sEn = (float*)(sm + OFF_EN);
    float* sWn = (float*)(sm + OFF_WN);
    int*   sY  = (int*)(sm + OFF_Y);
    float* sLs = (float*)(sm + OFF_LS);
    float* sPE = (float*)(sm + OFF_PE);
    float* sPW = (float*)(sm + OFF_PW);
    __shared__ int sFlag;

    const int t  = threadIdx.x;
    const int L  = t & 31;
    const int wi = t >> 5;
    const int b0 = blockIdx.x * BPC;

    // ---------- stage E: gmem [r][d] -> smem [d2][r] float2; fused |e|^2 ----------
    {
        const int r = t & 63, g = t >> 6;
        const float4* Er = (const float4*)(E + (size_t)r * ND);
        float enp = 0.f;
        #pragma unroll 4
        for (int k = 0; k < 32; ++k) {
            int c = g + (k << 2);
            float4 v = Er[c];
            enp = fmaf(v.x, v.x, enp); enp = fmaf(v.y, v.y, enp);
            enp = fmaf(v.z, v.z, enp); enp = fmaf(v.w, v.w, enp);
            // consecutive lanes -> consecutive r -> conflict-free STS.64
            *(float2*)((char*)sE + (size_t)(2 * c)     * 512 + r * 8) = make_float2(v.x, v.y);
            *(float2*)((char*)sE + (size_t)(2 * c + 1) * 512 + r * 8) = make_float2(v.z, v.w);
        }
        sPE[t] = enp;
    }
    // ---------- stage W chunk-major [c][b] float4; fused |w|^2 ----------
    {
        const int b = t & 31, g = t >> 5;
        const float4* Wb = (const float4*)(W + (size_t)(b0 + b) * ND);
        float wnp = 0.f;
        #pragma unroll 4
        for (int k = 0; k < 16; ++k) {
            int c = g + (k << 3);
            float4 v = Wb[c];
            wnp = fmaf(v.x, v.x, wnp); wnp = fmaf(v.y, v.y, wnp);
            wnp = fmaf(v.z, v.z, wnp); wnp = fmaf(v.w, v.w, wnp);
            sW4[c * 32 + b] = v;   // consecutive lanes -> consecutive 16B: conflict-free
        }
        sPW[t] = wnp;
    }
    // ---------- label argmax: warp wi handles rows 4wi..4wi+3 ----------
    {
        #pragma unroll
        for (int j = 0; j < 4; ++j) {
            int bl = wi * 4 + j;
            const float* Lr = Lb + (size_t)(b0 + bl) * NR;
            float lv = Lr[L]; int li = L;
            float l2 = Lr[L + 32];
            if (l2 > lv) { lv = l2; li = L + 32; }   // strict > keeps lower index on ties
            #pragma unroll
            for (int o = 16; o; o >>= 1) {
                float ov = __shfl_xor_sync(0xffffffffu, lv, o);
                int   oi = __shfl_xor_sync(0xffffffffu, li, o);
                if (ov > lv || (ov == lv && oi < li)) { lv = ov; li = oi; }
            }
            if (L == 0) sY[bl] = li;
        }
    }
    __syncthreads();

    // ---------- norm combines (visible to epilogue via post-mainloop barrier) ----------
    if (t < 64) {
        sEn[t] = sPE[t] + sPE[t + 64] + sPE[t + 128] + sPE[t + 192];
    } else if (t < 96) {
        int u = t - 64; float s = 0.f;
        #pragma unroll
        for (int k = 0; k < 8; ++k) s += sPW[u + 32 * k];
        sWn[u] = s;
    }

    // ================= mainloop: 8 warps = 4 b-groups x 2 k-slices =================
    const int G = wi & 3;        // b-group: b in [8G, 8G+8)
    const int s = wi >> 1 >> 1;  // k-slice (wi>>2)
    u64 acc[8][2] = {};          // [bb][r of lane's 2], f32x2 packed over d-parity
    {
        const char* eb = (const char*)sE + (size_t)s * 65536 + L * 16;
        const ulonglong2* wc = (const ulonglong2*)(sW4) + (size_t)s * 2048 + G * 8;
        #pragma unroll 2
        for (int j = 0; j < 64; ++j) {
            ulonglong2 eA = *(const ulonglong2*)(eb);        // d2 = 128s+2j : r0,r1
            ulonglong2 eB = *(const ulonglong2*)(eb + 512);  // d2 = 128s+2j+1
            eb += 1024;
            #pragma unroll
            for (int bb = 0; bb < 8; ++bb) {
                ulonglong2 wv = wc[bb];                      // {w(d0),w(d1)},{w(d2),w(d3)}
                fma2(acc[bb][0], wv.x, eA.x);
                fma2(acc[bb][1], wv.x, eA.y);
                fma2(acc[bb][0], wv.y, eB.x);
                fma2(acc[bb][1], wv.y, eB.y);
            }
            wc += 32;
        }
    }

    // k-slice 1 dumps partials (16B/lane stride: conflict-free)
    if (s == 1) {
        #pragma unroll
        for (int bb = 0; bb < 8; ++bb)
            sP[(G * 8 + bb) * 32 + L] = make_ulonglong2(acc[bb][0], acc[bb][1]);
    }
    __syncthreads();

    // ================= epilogue (k-slice 0 warps): combine, top-2, loss, pred =================
    if (s == 0) {
        float2 en2 = *(const float2*)(sEn + 2 * L);
        #pragma unroll
        for (int bb = 0; bb < 8; ++bb) {
            const int bl = G * 8 + bb;
            ulonglong2 p = sP[bl * 32 + L];
            float dot0 = hsum2(add2(acc[bb][0], p.x));   // dot(b, r=2L)
            float dot1 = hsum2(add2(acc[bb][1], p.y));   // dot(b, r=2L+1)
            float wn = sWn[bl];
            int   y  = sY[bl];
            float da = fmaf(-2.f, dot0, wn + en2.x);     // dist^2(b, 2L)
            float db = fmaf(-2.f, dot1, wn + en2.y);     // dist^2(b, 2L+1)
            float v1, v2; int i1;
            if (db > da) { v1 = db; i1 = 2 * L + 1; v2 = da; }
            else         { v1 = da; i1 = 2 * L;     v2 = db; }
            float pys = (y & 1) ? db : da;
            #pragma unroll
            for (int o = 16; o; o >>= 1) {
                float ov1 = __shfl_xor_sync(0xffffffffu, v1, o);
                int   oi1 = __shfl_xor_sync(0xffffffffu, i1, o);
                float ov2 = __shfl_xor_sync(0xffffffffu, v2, o);
                if (ov1 > v1 || (ov1 == v1 && oi1 < i1)) {
                    v2 = fmaxf(v1, ov2); v1 = ov1; i1 = oi1;
                } else {
                    v2 = fmaxf(v2, ov1);
                }
            }
            float plus  = __shfl_sync(0xffffffffu, pys, y >> 1);
            float minus = (i1 == y) ? v2 : v1;
            if (L == 0)
                sLs[bl] = 1.0f + sqrtf(fmaxf(plus, 0.f)) - sqrtf(fmaxf(minus, 0.f));
            float2 pr = make_float2((2 * L == i1) ? 1.f : 0.f,
                                    (2 * L + 1 == i1) ? 1.f : 0.f);
            *(float2*)(pred + (size_t)(b0 + bl) * NR + 2 * L) = pr;
        }
    }
    __syncthreads();

    // ================= per-CTA loss partial + deterministic last-CTA mean =================
    if (t < 32) {
        float sv = sLs[t];
        #pragma unroll
        for (int o = 16; o; o >>= 1) sv += __shfl_xor_sync(0xffffffffu, sv, o);
        if (t == 0) {
            g_part[blockIdx.x] = sv;
            __threadfence();
            int old = atomicAdd(&g_ctr, 1);
            sFlag = (old == GRID - 1) ? 1 : 0;
        }
    }
    __syncthreads();
    if (sFlag && t < 32) {
        float sv = 0.f;
        #pragma unroll
        for (int k = 0; k < GRID / 32; ++k) {
            float v;
            asm("ld.global.cg.f32 %0, [%1];" : "=f"(v) : "l"(g_part + t + 32 * k));
            sv += v;
        }
        #pragma unroll
        for (int o = 16; o; o >>= 1) sv += __shfl_xor_sync(0xffffffffu, sv, o);
        if (t == 0) { *lossp = sv * (1.0f / (float)NB); g_ctr = 0; }
    }
}

extern "C" void kernel_launch(void* const* d_in, const int* in_sizes, int n_in,
                              void* d_out, int out_size) {
    const float* W = nullptr; const float* E = nullptr; const float* L = nullptr;
    for (int i = 0; i < n_in; ++i) {
        if      (in_sizes[i] == NB * ND) W = (const float*)d_in[i];
        else if (in_sizes[i] == NR * ND) E = (const float*)d_in[i];
        else if (in_sizes[i] == NB * NR) L = (const float*)d_in[i];
    }
    float* out = (float*)d_out;
    cudaFuncSetAttribute(k_fused, cudaFuncAttributeMaxDynamicSharedMemorySize, SMEM_TOTAL);
    k_fused<<<GRID, 256, SMEM_TOTAL>>>(W, E, L, out, out + (out_size - 1));
}